// round 10
// baseline (speedup 1.0000x reference)
#include <cuda_runtime.h>

#define TB      16      // batch elements per CTA
#define THREADS 384     // 3 agents x 32 h-groups(4h) x 4 e-groups(4e)
typedef unsigned long long ull;

// smem float offsets (dup regions store every activation twice: [e][2k],[2k+1])
#define OFF_IN    0                      // [3][TB][80]   input dup (40 k-slots)
#define OFF_OEMB  (3*TB*80)              // [3][TB][256]  o_emb dup
#define OFF_OA    (OFF_OEMB + 3*TB*256)  // [3][TB][256]  oa_emb dup -> attn_out dup
#define OFF_K     (OFF_OA   + 3*TB*256)  // [3][TB][128]  K natural, later h1
#define OFF_V     (OFF_K    + 3*TB*128)  // [3][TB][128]  V natural
#define SMEM_FLOATS (OFF_V + 3*TB*128)   // 40704 floats = 159.0 KB

__device__ __forceinline__ ull pk2(float x, float y) {
    ull r; asm("mov.b64 %0,{%1,%2};" : "=l"(r) : "f"(x), "f"(y)); return r;
}
__device__ __forceinline__ void up2(ull v, float &x, float &y) {
    asm("mov.b64 {%0,%1},%2;" : "=f"(x), "=f"(y) : "l"(v));
}
__device__ __forceinline__ void fma2(ull &d, ull a, ull b) {
    asm("fma.rn.f32x2 %0,%1,%2,%0;" : "+l"(d) : "l"(a), "l"(b));
}
__device__ __forceinline__ float4 unpack2(ull A, ull B) {
    float a0,a1,a2,a3; up2(A,a0,a1); up2(B,a2,a3);
    return make_float4(a0,a1,a2,a3);
}
// store float4 v duplicated: (v.x,v.x,v.y,v.y)(v.z,v.z,v.w,v.w)
__device__ __forceinline__ void store_dup(float* dst, float4 v) {
    *(float4*)(dst)     = make_float4(v.x, v.x, v.y, v.y);
    *(float4*)(dst + 4) = make_float4(v.z, v.z, v.w, v.w);
}

// one e-row step: 4 k's of dup activations x 4 k's of weight pairs
#define ESTEP(A, B, p) { \
    ulonglong2 x01 = *(const ulonglong2*)(p); \
    ulonglong2 x23 = *(const ulonglong2*)((p) + 4); \
    fma2(A, x01.x, w0.x); fma2(B, x01.x, w0.y); \
    fma2(A, x01.y, w1.x); fma2(B, x01.y, w1.y); \
    fma2(A, x23.x, w2.x); fma2(B, x23.x, w2.y); \
    fma2(A, x23.y, w3.x); fma2(B, x23.y, w3.y); }

// A_e holds (h0,h0+1) partial pair, B_e holds (h0+2,h0+3), for e = eb..eb+3.
// sp: smem ptr to dup row of e=eb (DUPROW floats per e). Wp = W + h0.
template<int NQ, int KVALID, int DUPROW>
__device__ __forceinline__ void gemm4dup(const float* __restrict__ sp,
                                         const float* __restrict__ Wp,
                                         ull &A0, ull &A1, ull &A2, ull &A3,
                                         ull &B0, ull &B1, ull &B2, ull &B3)
{
    #pragma unroll
    for (int q = 0; q < NQ; q++) {
        const int k = q * 4;
        ulonglong2 zz; zz.x = 0ull; zz.y = 0ull;
        ulonglong2 w0 = (k+0 < KVALID) ? *(const ulonglong2*)(Wp + (k+0)*128) : zz;
        ulonglong2 w1 = (k+1 < KVALID) ? *(const ulonglong2*)(Wp + (k+1)*128) : zz;
        ulonglong2 w2 = (k+2 < KVALID) ? *(const ulonglong2*)(Wp + (k+2)*128) : zz;
        ulonglong2 w3 = (k+3 < KVALID) ? *(const ulonglong2*)(Wp + (k+3)*128) : zz;
        const float* p = sp + 2*k;
        ESTEP(A0, B0, p);
        ESTEP(A1, B1, p + DUPROW);
        ESTEP(A2, B2, p + 2*DUPROW);
        ESTEP(A3, B3, p + 3*DUPROW);
    }
}

__device__ __forceinline__ float4 leaky4(float4 v) {
    v.x = (v.x >= 0.f) ? v.x : 0.01f * v.x;
    v.y = (v.y >= 0.f) ? v.y : 0.01f * v.y;
    v.z = (v.z >= 0.f) ? v.z : 0.01f * v.z;
    v.w = (v.w >= 0.f) ? v.w : 0.01f * v.w;
    return v;
}

__global__ __launch_bounds__(THREADS)
void valuenet_kernel(
    const float* __restrict__ obs,  const float* __restrict__ act,
    const float* __restrict__ W_o,  const float* __restrict__ b_o,
    const float* __restrict__ W_oa, const float* __restrict__ b_oa,
    const float* __restrict__ Wq,   const float* __restrict__ bq,
    const float* __restrict__ Wk,   const float* __restrict__ bk,
    const float* __restrict__ Wv,   const float* __restrict__ bv,
    const float* __restrict__ Wc1,  const float* __restrict__ bc1,
    const float* __restrict__ Wc2,  const float* __restrict__ bc2,
    float* __restrict__ out)
{
    extern __shared__ float sm[];
    float* s_in   = sm + OFF_IN;
    float* s_oemb = sm + OFF_OEMB;  // dup
    float* s_oa   = sm + OFF_OA;    // dup: oa_emb -> attn_out
    float* s_K    = sm + OFF_K;     // natural; later h1
    float* s_V    = sm + OFF_V;     // natural

    const int t   = threadIdx.x;
    const int n   = t >> 7;        // agent 0..2 (uniform per warp)
    const int r   = t & 127;
    const int hg  = r & 31;        // h-group (4 channels), varies across lanes
    const int eg  = r >> 5;        // e-group 0..3 (uniform per warp)
    const int h0  = hg * 4;
    const int eb  = eg * 4;
    const int e0g = blockIdx.x * TB;

    // ---------------- P0: stage inputs (duplicated) ----------------
    for (int i = t; i < TB * 90; i += THREADS) {
        int e = i / 90, rr = i - e * 90;
        int nn = rr / 30, d = rr - nn * 30;
        float v = obs[(long)(e0g + e) * 90 + rr];
        float* p = &s_in[(nn * TB + e) * 80 + 2*d];
        p[0] = v; p[1] = v;
    }
    for (int i = t; i < TB * 27; i += THREADS) {
        int e = i / 27, rr = i - e * 27;
        int nn = rr / 9, d = 30 + (rr - nn * 9);
        float v = act[(long)(e0g + e) * 27 + rr];
        float* p = &s_in[(nn * TB + e) * 80 + 2*d];
        p[0] = v; p[1] = v;
    }
    for (int i = t; i < 3 * TB; i += THREADS) {   // pad slot d=39
        s_in[i * 80 + 78] = 0.f; s_in[i * 80 + 79] = 0.f;
    }
    __syncthreads();

    // ---------------- P1: per-agent embeds ----------------
    {
        const float* sp = s_in + (n * TB + eb) * 80;
        {   // o_emb
            float4 b = *(const float4*)(b_o + n*128 + h0);
            ull b01 = pk2(b.x, b.y), b23 = pk2(b.z, b.w);
            ull A0=b01,A1=b01,A2=b01,A3=b01, B0=b23,B1=b23,B2=b23,B3=b23;
            gemm4dup<8, 30, 80>(sp, W_o + n * 30 * 128 + h0, A0,A1,A2,A3,B0,B1,B2,B3);
            store_dup(&s_oemb[(n*TB + eb + 0)*256 + 2*h0], leaky4(unpack2(A0,B0)));
            store_dup(&s_oemb[(n*TB + eb + 1)*256 + 2*h0], leaky4(unpack2(A1,B1)));
            store_dup(&s_oemb[(n*TB + eb + 2)*256 + 2*h0], leaky4(unpack2(A2,B2)));
            store_dup(&s_oemb[(n*TB + eb + 3)*256 + 2*h0], leaky4(unpack2(A3,B3)));
        }
        {   // oa_emb
            float4 b = *(const float4*)(b_oa + n*128 + h0);
            ull b01 = pk2(b.x, b.y), b23 = pk2(b.z, b.w);
            ull A0=b01,A1=b01,A2=b01,A3=b01, B0=b23,B1=b23,B2=b23,B3=b23;
            gemm4dup<10, 39, 80>(sp, W_oa + n * 39 * 128 + h0, A0,A1,A2,A3,B0,B1,B2,B3);
            store_dup(&s_oa[(n*TB + eb + 0)*256 + 2*h0], leaky4(unpack2(A0,B0)));
            store_dup(&s_oa[(n*TB + eb + 1)*256 + 2*h0], leaky4(unpack2(A1,B1)));
            store_dup(&s_oa[(n*TB + eb + 2)*256 + 2*h0], leaky4(unpack2(A2,B2)));
            store_dup(&s_oa[(n*TB + eb + 3)*256 + 2*h0], leaky4(unpack2(A3,B3)));
        }
    }
    __syncthreads();

    // ---------------- P2: K, V, Q projections ----------------
    float4 qv0, qv1, qv2, qv3;   // this thread's Q slots (own e's, own h's)
    {
        const float* spA = s_oa   + (n * TB + eb) * 256;
        const float* spQ = s_oemb + (n * TB + eb) * 256;
        {   // K -> s_K natural
            float4 b = *(const float4*)(bk + h0);
            ull b01 = pk2(b.x, b.y), b23 = pk2(b.z, b.w);
            ull A0=b01,A1=b01,A2=b01,A3=b01, B0=b23,B1=b23,B2=b23,B3=b23;
            gemm4dup<32, 128, 256>(spA, Wk + h0, A0,A1,A2,A3,B0,B1,B2,B3);
            *(float4*)&s_K[(n*TB + eb + 0)*128 + h0] = unpack2(A0,B0);
            *(float4*)&s_K[(n*TB + eb + 1)*128 + h0] = unpack2(A1,B1);
            *(float4*)&s_K[(n*TB + eb + 2)*128 + h0] = unpack2(A2,B2);
            *(float4*)&s_K[(n*TB + eb + 3)*128 + h0] = unpack2(A3,B3);
        }
        {   // V -> s_V natural
            float4 b = *(const float4*)(bv + h0);
            ull b01 = pk2(b.x, b.y), b23 = pk2(b.z, b.w);
            ull A0=b01,A1=b01,A2=b01,A3=b01, B0=b23,B1=b23,B2=b23,B3=b23;
            gemm4dup<32, 128, 256>(spA, Wv + h0, A0,A1,A2,A3,B0,B1,B2,B3);
            *(float4*)&s_V[(n*TB + eb + 0)*128 + h0] = unpack2(A0,B0);
            *(float4*)&s_V[(n*TB + eb + 1)*128 + h0] = unpack2(A1,B1);
            *(float4*)&s_V[(n*TB + eb + 2)*128 + h0] = unpack2(A2,B2);
            *(float4*)&s_V[(n*TB + eb + 3)*128 + h0] = unpack2(A3,B3);
        }
        {   // Q -> registers
            float4 b = *(const float4*)(bq + h0);
            ull b01 = pk2(b.x, b.y), b23 = pk2(b.z, b.w);
            ull A0=b01,A1=b01,A2=b01,A3=b01, B0=b23,B1=b23,B2=b23,B3=b23;
            gemm4dup<32, 128, 256>(spQ, Wq + h0, A0,A1,A2,A3,B0,B1,B2,B3);
            qv0 = unpack2(A0,B0); qv1 = unpack2(A1,B1);
            qv2 = unpack2(A2,B2); qv3 = unpack2(A3,B3);
        }
    }
    __syncthreads();   // K, V visible to all agents

    // ---------------- P3: 3-agent masked attention ----------------
    // head = hg>>3 (8 lanes x 4 dims = 32 head dims); xor-shuffle over 8 lanes.
    {
        const float scale = 0.17677669529663689f;  // 1/sqrt(32)
        #define ATTN_E(EI, QV) { \
            const int e = eb + EI; \
            float4 q = QV; \
            float4 k0 = *(float4*)&s_K[(0*TB + e)*128 + h0]; \
            float4 k1 = *(float4*)&s_K[(1*TB + e)*128 + h0]; \
            float4 k2 = *(float4*)&s_K[(2*TB + e)*128 + h0]; \
            float s0 = q.x*k0.x + q.y*k0.y + q.z*k0.z + q.w*k0.w; \
            float s1 = q.x*k1.x + q.y*k1.y + q.z*k1.z + q.w*k1.w; \
            float s2 = q.x*k2.x + q.y*k2.y + q.z*k2.z + q.w*k2.w; \
            s0 += __shfl_xor_sync(0xffffffffu, s0, 4); \
            s1 += __shfl_xor_sync(0xffffffffu, s1, 4); \
            s2 += __shfl_xor_sync(0xffffffffu, s2, 4); \
            s0 += __shfl_xor_sync(0xffffffffu, s0, 2); \
            s1 += __shfl_xor_sync(0xffffffffu, s1, 2); \
            s2 += __shfl_xor_sync(0xffffffffu, s2, 2); \
            s0 += __shfl_xor_sync(0xffffffffu, s0, 1); \
            s1 += __shfl_xor_sync(0xffffffffu, s1, 1); \
            s2 += __shfl_xor_sync(0xffffffffu, s2, 1); \
            s0 *= scale; s1 *= scale; s2 *= scale; \
            if (n == 0)      s0 -= 1e10f; \
            else if (n == 1) s1 -= 1e10f; \
            else             s2 -= 1e10f; \
            float mx  = fmaxf(s0, fmaxf(s1, s2)); \
            float p0  = __expf(s0 - mx); \
            float p1  = __expf(s1 - mx); \
            float p2  = __expf(s2 - mx); \
            float inv = 1.0f / (p0 + p1 + p2); \
            p0 *= inv; p1 *= inv; p2 *= inv; \
            float4 v0 = *(float4*)&s_V[(0*TB + e)*128 + h0]; \
            float4 v1 = *(float4*)&s_V[(1*TB + e)*128 + h0]; \
            float4 v2 = *(float4*)&s_V[(2*TB + e)*128 + h0]; \
            float4 ao; \
            ao.x = p0*v0.x + p1*v1.x + p2*v2.x; \
            ao.y = p0*v0.y + p1*v1.y + p2*v2.y; \
            ao.z = p0*v0.z + p1*v1.z + p2*v2.z; \
            ao.w = p0*v0.w + p1*v1.w + p2*v2.w; \
            store_dup(&s_oa[(n*TB + e)*256 + 2*h0], ao); }
        ATTN_E(0, qv0); ATTN_E(1, qv1); ATTN_E(2, qv2); ATTN_E(3, qv3);
        #undef ATTN_E
    }
    __syncthreads();

    // ---------------- P4: critic layer 1 (256 -> 128) ----------------
    {
        float4 b = *(const float4*)(bc1 + n*128 + h0);
        ull b01 = pk2(b.x, b.y), b23 = pk2(b.z, b.w);
        ull A0=b01,A1=b01,A2=b01,A3=b01, B0=b23,B1=b23,B2=b23,B3=b23;
        gemm4dup<32, 128, 256>(s_oemb + (n*TB + eb) * 256,
                               Wc1 + (size_t)n * 256 * 128 + h0,
                               A0,A1,A2,A3,B0,B1,B2,B3);
        gemm4dup<32, 128, 256>(s_oa + (n*TB + eb) * 256,
                               Wc1 + ((size_t)n * 256 + 128) * 128 + h0,
                               A0,A1,A2,A3,B0,B1,B2,B3);
        *(float4*)&s_K[(n*TB + eb + 0)*128 + h0] = leaky4(unpack2(A0,B0));  // h1
        *(float4*)&s_K[(n*TB + eb + 1)*128 + h0] = leaky4(unpack2(A1,B1));
        *(float4*)&s_K[(n*TB + eb + 2)*128 + h0] = leaky4(unpack2(A2,B2));
        *(float4*)&s_K[(n*TB + eb + 3)*128 + h0] = leaky4(unpack2(A3,B3));
    }
    __syncthreads();

    // ---------------- P5: critic layer 2 (128 -> 9) + store ----------------
    for (int idx = t; idx < TB * 27; idx += THREADS) {
        int e = idx / 27, rr = idx - e * 27;
        int nn = rr / 9,  a = rr - nn * 9;
        float acc = bc2[nn * 9 + a];
        const float* hp = &s_K[(nn * TB + e) * 128];
        const float* wp = Wc2 + (size_t)nn * 128 * 9 + a;
        #pragma unroll 8
        for (int j = 0; j < 128; j += 4) {
            float4 x = *(const float4*)(hp + j);
            acc += x.x * wp[(j+0)*9] + x.y * wp[(j+1)*9]
                 + x.z * wp[(j+2)*9] + x.w * wp[(j+3)*9];
        }
        out[(long)(e0g + e) * 27 + rr] = acc;
    }
}

extern "C" void kernel_launch(void* const* d_in, const int* in_sizes, int n_in,
                              void* d_out, int out_size) {
    const float* obs  = (const float*)d_in[0];
    const float* act  = (const float*)d_in[1];
    const float* W_o  = (const float*)d_in[2];
    const float* b_o  = (const float*)d_in[3];
    const float* W_oa = (const float*)d_in[4];
    const float* b_oa = (const float*)d_in[5];
    const float* Wq   = (const float*)d_in[6];
    const float* bq   = (const float*)d_in[7];
    const float* Wk   = (const float*)d_in[8];
    const float* bk   = (const float*)d_in[9];
    const float* Wv   = (const float*)d_in[10];
    const float* bv   = (const float*)d_in[11];
    const float* Wc1  = (const float*)d_in[12];
    const float* bc1  = (const float*)d_in[13];
    const float* Wc2  = (const float*)d_in[14];
    const float* bc2  = (const float*)d_in[15];
    float* out = (float*)d_out;

    const int batch = in_sizes[0] / (3 * 30);   // 131072
    const int grid  = batch / TB;               // 8192
    const size_t smem = SMEM_FLOATS * sizeof(float);  // 159.0 KB

    cudaFuncSetAttribute(valuenet_kernel,
                         cudaFuncAttributeMaxDynamicSharedMemorySize, (int)smem);
    valuenet_kernel<<<grid, THREADS, smem>>>(
        obs, act, W_o, b_o, W_oa, b_oa, Wq, bq, Wk, bk, Wv, bv,
        Wc1, bc1, Wc2, bc2, out);
}

// round 11
// speedup vs baseline: 2.9199x; 2.9199x over previous
#include <cuda_runtime.h>

#define TB      32
#define THREADS 384
#define LDIN    52      // s_in row stride (48 k-slots + 4 pad)
#define LDA     132     // s_oemb / s_oa row stride (128 + 4 pad)
#define LDKV    128     // s_K / s_V row stride

// smem float offsets
#define SM_IN    0
#define SM_OEMB  (3*TB*LDIN)
#define SM_OA    (SM_OEMB + 3*TB*LDA)
#define SM_K     (SM_OA   + 3*TB*LDA)
#define SM_V     (SM_K    + 3*TB*LDKV)
#define SMEM_FLOATS (SM_V + 3*TB*LDKV)   // 54912 floats = 214.5 KB

// weight-fragment scratch (uint4 units). Section bases in uint4:
#define F_WO   0
#define F_WOA  4608
#define F_WQ   9216
#define F_WK   13312
#define F_WV   17408
#define F_WC1  21504
#define F_TOTAL 46080        // 184320 floats
__device__ uint4 g_fragv[F_TOTAL];

__device__ __forceinline__ unsigned tf32r(float x) {
    unsigned u; asm("cvt.rna.tf32.f32 %0, %1;" : "=r"(u) : "f"(x)); return u;
}

// ---------------- prep: weights -> tf32 B-fragments ----------------
// layout per matrix/agent: [nt(16)][kp(KPTOT)][lane(32)][r(4)]
// r=0: k=16kp+lane%4      r=1: +4      r=2: +8      r=3: +12  ... precisely:
// k = kp*16 + (r>>1)*8 + (r&1)*4 + (lane&3);  n = nt*8 + (lane>>2)
__global__ void prep_kernel(const float* __restrict__ W_o,  const float* __restrict__ W_oa,
                            const float* __restrict__ Wq,   const float* __restrict__ Wk,
                            const float* __restrict__ Wv,   const float* __restrict__ Wc1)
{
    int idx = blockIdx.x * 256 + threadIdx.x;
    if (idx >= 184320) return;
    const float* src; int base, kptot, kvalid, astride;
    if      (idx < 18432) { src = W_o;  base = 0;     kptot = 3;  kvalid = 30;  astride = 30*128;  }
    else if (idx < 36864) { src = W_oa; base = 18432; kptot = 3;  kvalid = 39;  astride = 39*128;  }
    else if (idx < 53248) { src = Wq;   base = 36864; kptot = 8;  kvalid = 128; astride = 0;       }
    else if (idx < 69632) { src = Wk;   base = 53248; kptot = 8;  kvalid = 128; astride = 0;       }
    else if (idx < 86016) { src = Wv;   base = 69632; kptot = 8;  kvalid = 128; astride = 0;       }
    else                  { src = Wc1;  base = 86016; kptot = 16; kvalid = 256; astride = 256*128; }
    int m   = idx - base;
    int per = 16 * kptot * 128;
    int ag  = m / per;  m -= ag * per;
    int nt  = m / (kptot * 128);
    int m2  = m - nt * (kptot * 128);
    int kp  = m2 >> 7, li = m2 & 127;
    int lane = li >> 2, rr = li & 3;
    int k = kp*16 + (rr>>1)*8 + (rr&1)*4 + (lane&3);
    int n = nt*8 + (lane>>2);
    float v = (k < kvalid) ? src[(size_t)ag*astride + k*128 + n] : 0.f;
    ((unsigned*)g_fragv)[idx] = tf32r(v);
}

// ---------------- warp-level tensor GEMM ----------------
__device__ __forceinline__ void mma8(float* d, const unsigned* a, unsigned b0, unsigned b1) {
    asm volatile("mma.sync.aligned.m16n8k8.row.col.f32.tf32.tf32.f32 "
                 "{%0,%1,%2,%3}, {%4,%5,%6,%7}, {%8,%9}, {%0,%1,%2,%3};"
                 : "+f"(d[0]), "+f"(d[1]), "+f"(d[2]), "+f"(d[3])
                 : "r"(a[0]), "r"(a[1]), "r"(a[2]), "r"(a[3]), "r"(b0), "r"(b1));
}

// D[32 x 32cols-of-warp] += A[32 x 16*KPC] * W-fragments
// Abase: smem row0 of the agent's 32-row block (tf32 bits stored as float), lda stride.
// frag: uint4* positioned at this (matrix, agent, warpN, kp-offset); per-(ntLocal,kp)
//       fragment at frag[(nt*KPT + kp)*32 + lane].
template<int KPC, int KPT>
__device__ __forceinline__ void warp_gemm(const float* __restrict__ Abase, int lda,
                                          const uint4* __restrict__ frag,
                                          int lane, float (*d)[4][4])
{
    const int ra = lane >> 2, ca = lane & 3;
    #pragma unroll 2
    for (int kp = 0; kp < KPC; kp++) {
        unsigned a[2][2][4];
        #pragma unroll
        for (int mt = 0; mt < 2; mt++)
            #pragma unroll
            for (int tt = 0; tt < 2; tt++) {
                const float* p = Abase + (ra + mt*16)*lda + kp*16 + tt*8 + ca;
                a[mt][tt][0] = __float_as_uint(p[0]);
                a[mt][tt][1] = __float_as_uint(p[8*lda]);
                a[mt][tt][2] = __float_as_uint(p[4]);
                a[mt][tt][3] = __float_as_uint(p[8*lda + 4]);
            }
        #pragma unroll
        for (int nt = 0; nt < 4; nt++) {
            uint4 b = frag[(nt*KPT + kp)*32 + lane];
            #pragma unroll
            for (int mt = 0; mt < 2; mt++) {
                mma8(d[mt][nt], a[mt][0], b.x, b.y);
                mma8(d[mt][nt], a[mt][1], b.z, b.w);
            }
        }
    }
}

#define K_PLAIN 0   // +bias
#define K_LKYRND 1  // +bias, leaky, tf32-round (feeds later mma A)
#define K_LKY 2     // +bias, leaky (scalar consumer)

__device__ __forceinline__ void store_d(float (*d)[4][4], float* __restrict__ dst, int ldd,
                                        const float* __restrict__ bias, int colBase,
                                        int lane, int kind)
{
    const int rr = lane >> 2, cc = (lane & 3) * 2;
    #pragma unroll
    for (int nt = 0; nt < 4; nt++) {
        int col = colBase + nt*8 + cc;
        float2 b2 = *(const float2*)(bias + col);
        #pragma unroll
        for (int mt = 0; mt < 2; mt++) {
            float v0 = d[mt][nt][0] + b2.x, v1 = d[mt][nt][1] + b2.y;
            float v2 = d[mt][nt][2] + b2.x, v3 = d[mt][nt][3] + b2.y;
            if (kind != K_PLAIN) {
                v0 = (v0 >= 0.f) ? v0 : 0.01f*v0;  v1 = (v1 >= 0.f) ? v1 : 0.01f*v1;
                v2 = (v2 >= 0.f) ? v2 : 0.01f*v2;  v3 = (v3 >= 0.f) ? v3 : 0.01f*v3;
            }
            if (kind == K_LKYRND) {
                v0 = __uint_as_float(tf32r(v0)); v1 = __uint_as_float(tf32r(v1));
                v2 = __uint_as_float(tf32r(v2)); v3 = __uint_as_float(tf32r(v3));
            }
            *(float2*)&dst[(rr + mt*16)*ldd + col]     = make_float2(v0, v1);
            *(float2*)&dst[(rr + 8 + mt*16)*ldd + col] = make_float2(v2, v3);
        }
    }
}

__device__ __forceinline__ void zero_d(float (*d)[4][4]) {
    #pragma unroll
    for (int mt = 0; mt < 2; mt++)
        #pragma unroll
        for (int nt = 0; nt < 4; nt++)
            #pragma unroll
            for (int i = 0; i < 4; i++) d[mt][nt][i] = 0.f;
}

__global__ __launch_bounds__(THREADS)
void valuenet_kernel(
    const float* __restrict__ obs,  const float* __restrict__ act,
    const float* __restrict__ b_o,  const float* __restrict__ b_oa,
    const float* __restrict__ bq,   const float* __restrict__ bk,
    const float* __restrict__ bv,   const float* __restrict__ bc1,
    const float* __restrict__ Wc2,  const float* __restrict__ bc2,
    float* __restrict__ out)
{
    extern __shared__ float sm[];
    float* s_in   = sm + SM_IN;
    float* s_oemb = sm + SM_OEMB;
    float* s_oa   = sm + SM_OA;   // oa_emb -> Q -> attn_out
    float* s_K    = sm + SM_K;    // K, later h1
    float* s_V    = sm + SM_V;

    const int t    = threadIdx.x;
    const int w    = t >> 5, lane = t & 31;
    const int ag   = w >> 2, wn = w & 3;     // agent, N-warp
    const int e0g  = blockIdx.x * TB;

    // ---------------- P0: stage inputs (tf32-rounded) ----------------
    for (int i = t; i < TB * 90; i += THREADS) {
        int e = i / 90, rr = i - e * 90;
        int nn = rr / 30, dd = rr - nn * 30;
        s_in[(nn * TB + e) * LDIN + dd] =
            __uint_as_float(tf32r(obs[(long)(e0g + e) * 90 + rr]));
    }
    for (int i = t; i < TB * 27; i += THREADS) {
        int e = i / 27, rr = i - e * 27;
        int nn = rr / 9, dd = 30 + (rr - nn * 9);
        s_in[(nn * TB + e) * LDIN + dd] =
            __uint_as_float(tf32r(act[(long)(e0g + e) * 27 + rr]));
    }
    for (int i = t; i < 3 * TB * 9; i += THREADS) {  // zero k-slots 39..47
        int row = i / 9, kk = 39 + (i - (i/9)*9);
        s_in[row * LDIN + kk] = 0.f;
    }
    __syncthreads();

    // ---------------- P1: per-agent embeds (tensor) ----------------
    {
        float d[2][4][4];
        zero_d(d);
        warp_gemm<3,3>(s_in + ag*TB*LDIN, LDIN,
                       g_fragv + F_WO + ag*1536 + wn*384, lane, d);
        store_d(d, s_oemb + ag*TB*LDA, LDA, b_o + ag*128, wn*32, lane, K_LKYRND);
        zero_d(d);
        warp_gemm<3,3>(s_in + ag*TB*LDIN, LDIN,
                       g_fragv + F_WOA + ag*1536 + wn*384, lane, d);
        store_d(d, s_oa + ag*TB*LDA, LDA, b_oa + ag*128, wn*32, lane, K_LKYRND);
    }
    __syncthreads();

    // ---------------- P2a: K and V (tensor, read oa_emb) ----------------
    {
        float d[2][4][4];
        zero_d(d);
        warp_gemm<8,8>(s_oa + ag*TB*LDA, LDA, g_fragv + F_WK + wn*1024, lane, d);
        store_d(d, s_K + ag*TB*LDKV, LDKV, bk, wn*32, lane, K_PLAIN);
        zero_d(d);
        warp_gemm<8,8>(s_oa + ag*TB*LDA, LDA, g_fragv + F_WV + wn*1024, lane, d);
        store_d(d, s_V + ag*TB*LDKV, LDKV, bv, wn*32, lane, K_PLAIN);
    }
    __syncthreads();

    // ---------------- P2b: Q (tensor, oa region becomes Q) ----------------
    {
        float d[2][4][4];
        zero_d(d);
        warp_gemm<8,8>(s_oemb + ag*TB*LDA, LDA, g_fragv + F_WQ + wn*1024, lane, d);
        store_d(d, s_oa + ag*TB*LDA, LDA, bq, wn*32, lane, K_PLAIN);
    }
    __syncthreads();

    // ---------------- P3: 3-agent masked attention (scalar fp32) ----------------
    {
        const int n  = t >> 7;         // agent
        const int r  = t & 127;
        const int hg = r & 31, eg = r >> 5;
        const int h0 = hg * 4, eb = eg * 8;
        const float scale = 0.17677669529663689f;  // 1/sqrt(32)
        #pragma unroll
        for (int ei = 0; ei < 8; ei++) {
            const int e = eb + ei;
            float4 q  = *(float4*)&s_oa[(n*TB + e)*LDA + h0];
            float4 k0 = *(float4*)&s_K[(0*TB + e)*LDKV + h0];
            float4 k1 = *(float4*)&s_K[(1*TB + e)*LDKV + h0];
            float4 k2 = *(float4*)&s_K[(2*TB + e)*LDKV + h0];
            float s0 = q.x*k0.x + q.y*k0.y + q.z*k0.z + q.w*k0.w;
            float s1 = q.x*k1.x + q.y*k1.y + q.z*k1.z + q.w*k1.w;
            float s2 = q.x*k2.x + q.y*k2.y + q.z*k2.z + q.w*k2.w;
            #pragma unroll
            for (int off = 4; off > 0; off >>= 1) {
                s0 += __shfl_xor_sync(0xffffffffu, s0, off);
                s1 += __shfl_xor_sync(0xffffffffu, s1, off);
                s2 += __shfl_xor_sync(0xffffffffu, s2, off);
            }
            s0 *= scale; s1 *= scale; s2 *= scale;
            if (n == 0)      s0 -= 1e10f;
            else if (n == 1) s1 -= 1e10f;
            else             s2 -= 1e10f;
            float mx  = fmaxf(s0, fmaxf(s1, s2));
            float p0  = __expf(s0 - mx);
            float p1  = __expf(s1 - mx);
            float p2  = __expf(s2 - mx);
            float inv = 1.0f / (p0 + p1 + p2);
            p0 *= inv; p1 *= inv; p2 *= inv;
            float4 v0 = *(float4*)&s_V[(0*TB + e)*LDKV + h0];
            float4 v1 = *(float4*)&s_V[(1*TB + e)*LDKV + h0];
            float4 v2 = *(float4*)&s_V[(2*TB + e)*LDKV + h0];
            float4 ao;
            ao.x = __uint_as_float(tf32r(p0*v0.x + p1*v1.x + p2*v2.x));
            ao.y = __uint_as_float(tf32r(p0*v0.y + p1*v1.y + p2*v2.y));
            ao.z = __uint_as_float(tf32r(p0*v0.z + p1*v1.z + p2*v2.z));
            ao.w = __uint_as_float(tf32r(p0*v0.w + p1*v1.w + p2*v2.w));
            *(float4*)&s_oa[(n*TB + e)*LDA + h0] = ao;   // attn_out (own Q slots)
        }
    }
    __syncthreads();

    // ---------------- P4: critic layer 1 (tensor, 256 -> 128) ----------------
    {
        float d[2][4][4];
        zero_d(d);
        const uint4* fc = g_fragv + F_WC1 + ag*8192 + wn*2048;   // KPT=16
        warp_gemm<8,16>(s_oemb + ag*TB*LDA, LDA, fc, lane, d);           // kp 0..7
        warp_gemm<8,16>(s_oa   + ag*TB*LDA, LDA, fc + 8*32, lane, d);    // kp 8..15
        store_d(d, s_K + ag*TB*LDKV, LDKV, bc1 + ag*128, wn*32, lane, K_LKY);  // h1
    }
    __syncthreads();

    // ---------------- P5: critic layer 2 (128 -> 9, scalar) + store ----------------
    for (int idx = t; idx < TB * 27; idx += THREADS) {
        int e = idx / 27, rr = idx - e * 27;
        int nn = rr / 9,  a = rr - nn * 9;
        float acc = bc2[nn * 9 + a];
        const float* hp = &s_K[(nn * TB + e) * LDKV];
        const float* wp = Wc2 + (size_t)nn * 128 * 9 + a;
        #pragma unroll 8
        for (int j = 0; j < 128; j += 4) {
            float4 x = *(const float4*)(hp + j);
            acc += x.x * wp[(j+0)*9] + x.y * wp[(j+1)*9]
                 + x.z * wp[(j+2)*9] + x.w * wp[(j+3)*9];
        }
        out[(long)(e0g + e) * 27 + rr] = acc;
    }
}

extern "C" void kernel_launch(void* const* d_in, const int* in_sizes, int n_in,
                              void* d_out, int out_size) {
    const float* obs  = (const float*)d_in[0];
    const float* act  = (const float*)d_in[1];
    const float* W_o  = (const float*)d_in[2];
    const float* b_o  = (const float*)d_in[3];
    const float* W_oa = (const float*)d_in[4];
    const float* b_oa = (const float*)d_in[5];
    const float* Wq   = (const float*)d_in[6];
    const float* bq   = (const float*)d_in[7];
    const float* Wk   = (const float*)d_in[8];
    const float* bk   = (const float*)d_in[9];
    const float* Wv   = (const float*)d_in[10];
    const float* bv   = (const float*)d_in[11];
    const float* Wc1  = (const float*)d_in[12];
    const float* bc1  = (const float*)d_in[13];
    const float* Wc2  = (const float*)d_in[14];
    const float* bc2  = (const float*)d_in[15];
    float* out = (float*)d_out;

    const int batch = in_sizes[0] / (3 * 30);   // 131072
    const int grid  = batch / TB;               // 4096
    const size_t smem = SMEM_FLOATS * sizeof(float);  // 214.5 KB

    prep_kernel<<<720, 256>>>(W_o, W_oa, Wq, Wk, Wv, Wc1);

    cudaFuncSetAttribute(valuenet_kernel,
                         cudaFuncAttributeMaxDynamicSharedMemorySize, (int)smem);
    valuenet_kernel<<<grid, THREADS, smem>>>(
        obs, act, b_o, b_oa, bq, bk, bv, bc1, Wc2, bc2, out);
}

// round 13
// speedup vs baseline: 4.4893x; 1.5375x over previous
#include <cuda_runtime.h>

#define TB      32
#define THREADS 384
#define LDIN    52      // s_in row stride (48 k-slots + 4 pad)
#define LDA     132     // activation row stride (128 + 4 pad)

// smem float offsets
#define SM_IN    0
#define SM_OEMB  (3*TB*LDIN)
#define SM_OA    (SM_OEMB + 3*TB*LDA)
#define SM_K     (SM_OA   + 3*TB*LDA)
#define SM_V     (SM_K    + 3*TB*LDA)
#define SMEM_FLOATS (SM_V + 3*TB*LDA)   // 55680 floats = 217.5 KB

// weight-fragment scratch (uint4 units). Section bases in uint4:
#define F_WO   0
#define F_WOA  4608
#define F_WQ   9216
#define F_WK   13312
#define F_WV   17408
#define F_WC1  21504
#define F_WC2  46080
#define F_TOTAL 47616        // 190464 floats
__device__ uint4 g_fragv[F_TOTAL];

__device__ __forceinline__ unsigned tf32r(float x) {
    unsigned u; asm("cvt.rna.tf32.f32 %0, %1;" : "=r"(u) : "f"(x)); return u;
}

// ---------------- prep: weights -> tf32 B-fragments ----------------
// layout per matrix/agent: [nt][kp][lane][r];  k = kp*16+(r>>1)*8+(r&1)*4+(lane&3),
// n = nt*8 + (lane>>2)
__global__ void prep_kernel(const float* __restrict__ W_o,  const float* __restrict__ W_oa,
                            const float* __restrict__ Wq,   const float* __restrict__ Wk,
                            const float* __restrict__ Wv,   const float* __restrict__ Wc1,
                            const float* __restrict__ Wc2)
{
    int idx = blockIdx.x * 256 + threadIdx.x;
    if (idx >= 190464) return;
    float v;
    if (idx < 184320) {
        const float* src; int base, kptot, kvalid, astride;
        if      (idx < 18432) { src = W_o;  base = 0;     kptot = 3;  kvalid = 30;  astride = 30*128;  }
        else if (idx < 36864) { src = W_oa; base = 18432; kptot = 3;  kvalid = 39;  astride = 39*128;  }
        else if (idx < 53248) { src = Wq;   base = 36864; kptot = 8;  kvalid = 128; astride = 0;       }
        else if (idx < 69632) { src = Wk;   base = 53248; kptot = 8;  kvalid = 128; astride = 0;       }
        else if (idx < 86016) { src = Wv;   base = 69632; kptot = 8;  kvalid = 128; astride = 0;       }
        else                  { src = Wc1;  base = 86016; kptot = 16; kvalid = 256; astride = 256*128; }
        int m   = idx - base;
        int per = 16 * kptot * 128;
        int ag  = m / per;  m -= ag * per;
        int nt  = m / (kptot * 128);
        int m2  = m - nt * (kptot * 128);
        int kp  = m2 >> 7, li = m2 & 127;
        int lane = li >> 2, rr = li & 3;
        int k = kp*16 + (rr>>1)*8 + (rr&1)*4 + (lane&3);
        int n = nt*8 + (lane>>2);
        v = (k < kvalid) ? src[(size_t)ag*astride + k*128 + n] : 0.f;
    } else {
        // Wc2: [3][128][9], N padded to 16. [ag][nt(2)][kp(8)][lane][r]
        int m  = idx - 184320;
        int ag = m / 2048; m -= ag * 2048;
        int nt = m >> 10;  m &= 1023;
        int kp = m >> 7;
        int li = m & 127;
        int lane = li >> 2, rr = li & 3;
        int k = kp*16 + (rr>>1)*8 + (rr&1)*4 + (lane&3);
        int n = nt*8 + (lane>>2);
        v = (n < 9) ? Wc2[ag*1152 + k*9 + n] : 0.f;
    }
    ((unsigned*)g_fragv)[idx] = tf32r(v);
}

// ---------------- warp-level tensor GEMM primitives ----------------
__device__ __forceinline__ void mma8(float* d, const unsigned* a, unsigned b0, unsigned b1) {
    asm volatile("mma.sync.aligned.m16n8k8.row.col.f32.tf32.tf32.f32 "
                 "{%0,%1,%2,%3}, {%4,%5,%6,%7}, {%8,%9}, {%0,%1,%2,%3};"
                 : "+f"(d[0]), "+f"(d[1]), "+f"(d[2]), "+f"(d[3])
                 : "r"(a[0]), "r"(a[1]), "r"(a[2]), "r"(a[3]), "r"(b0), "r"(b1));
}

#define LOAD_AFRAG(a, Abase, lda, kp) { \
    _Pragma("unroll") \
    for (int mt = 0; mt < 2; mt++) \
        _Pragma("unroll") \
        for (int tt = 0; tt < 2; tt++) { \
            const float* p = (Abase) + (ra + mt*16)*(lda) + (kp)*16 + tt*8 + ca; \
            a[mt][tt][0] = __float_as_uint(p[0]); \
            a[mt][tt][1] = __float_as_uint(p[8*(lda)]); \
            a[mt][tt][2] = __float_as_uint(p[4]); \
            a[mt][tt][3] = __float_as_uint(p[8*(lda) + 4]); \
        } }

template<int KPC, int KPT>
__device__ __forceinline__ void warp_gemm(const float* __restrict__ Abase, int lda,
                                          const uint4* __restrict__ frag,
                                          int lane, float (*d)[4][4])
{
    const int ra = lane >> 2, ca = lane & 3;
    #pragma unroll 2
    for (int kp = 0; kp < KPC; kp++) {
        unsigned a[2][2][4];
        LOAD_AFRAG(a, Abase, lda, kp);
        #pragma unroll
        for (int nt = 0; nt < 4; nt++) {
            uint4 b = frag[(nt*KPT + kp)*32 + lane];
            #pragma unroll
            for (int mt = 0; mt < 2; mt++) {
                mma8(d[mt][nt], a[mt][0], b.x, b.y);
                mma8(d[mt][nt], a[mt][1], b.z, b.w);
            }
        }
    }
}

// two GEMMs sharing the same A fragments (halves A-LDS traffic)
template<int KPC, int KPT>
__device__ __forceinline__ void warp_gemm_dual(const float* __restrict__ Abase, int lda,
                                               const uint4* __restrict__ f1,
                                               const uint4* __restrict__ f2,
                                               int lane, float (*d1)[4][4], float (*d2)[4][4])
{
    const int ra = lane >> 2, ca = lane & 3;
    #pragma unroll 2
    for (int kp = 0; kp < KPC; kp++) {
        unsigned a[2][2][4];
        LOAD_AFRAG(a, Abase, lda, kp);
        #pragma unroll
        for (int nt = 0; nt < 4; nt++) {
            uint4 b = f1[(nt*KPT + kp)*32 + lane];
            #pragma unroll
            for (int mt = 0; mt < 2; mt++) {
                mma8(d1[mt][nt], a[mt][0], b.x, b.y);
                mma8(d1[mt][nt], a[mt][1], b.z, b.w);
            }
            uint4 c = f2[(nt*KPT + kp)*32 + lane];
            #pragma unroll
            for (int mt = 0; mt < 2; mt++) {
                mma8(d2[mt][nt], a[mt][0], c.x, c.y);
                mma8(d2[mt][nt], a[mt][1], c.z, c.w);
            }
        }
    }
}

#define K_PLAIN 0
#define K_LKYRND 1

__device__ __forceinline__ void store_d(float (*d)[4][4], float* __restrict__ dst, int ldd,
                                        const float* __restrict__ bias, int colBase,
                                        int lane, int kind)
{
    const int rr = lane >> 2, cc = (lane & 3) * 2;
    #pragma unroll
    for (int nt = 0; nt < 4; nt++) {
        int col = colBase + nt*8 + cc;
        float2 b2 = *(const float2*)(bias + col);
        #pragma unroll
        for (int mt = 0; mt < 2; mt++) {
            float v0 = d[mt][nt][0] + b2.x, v1 = d[mt][nt][1] + b2.y;
            float v2 = d[mt][nt][2] + b2.x, v3 = d[mt][nt][3] + b2.y;
            if (kind == K_LKYRND) {
                v0 = (v0 >= 0.f) ? v0 : 0.01f*v0;  v1 = (v1 >= 0.f) ? v1 : 0.01f*v1;
                v2 = (v2 >= 0.f) ? v2 : 0.01f*v2;  v3 = (v3 >= 0.f) ? v3 : 0.01f*v3;
                v0 = __uint_as_float(tf32r(v0)); v1 = __uint_as_float(tf32r(v1));
                v2 = __uint_as_float(tf32r(v2)); v3 = __uint_as_float(tf32r(v3));
            }
            *(float2*)&dst[(rr + mt*16)*ldd + col]     = make_float2(v0, v1);
            *(float2*)&dst[(rr + 8 + mt*16)*ldd + col] = make_float2(v2, v3);
        }
    }
}

__device__ __forceinline__ void zero_d(float (*d)[4][4]) {
    #pragma unroll
    for (int mt = 0; mt < 2; mt++)
        #pragma unroll
        for (int nt = 0; nt < 4; nt++)
            #pragma unroll
            for (int i = 0; i < 4; i++) d[mt][nt][i] = 0.f;
}

__global__ __launch_bounds__(THREADS)
void valuenet_kernel(
    const float* __restrict__ obs,  const float* __restrict__ act,
    const float* __restrict__ b_o,  const float* __restrict__ b_oa,
    const float* __restrict__ bq,   const float* __restrict__ bk,
    const float* __restrict__ bv,   const float* __restrict__ bc1,
    const float* __restrict__ bc2,  float* __restrict__ out)
{
    extern __shared__ float sm[];
    float* s_in   = sm + SM_IN;     // inputs; later P5 partial scratch
    float* s_oemb = sm + SM_OEMB;
    float* s_oa   = sm + SM_OA;     // oa_emb -> Q -> attn_out
    float* s_K    = sm + SM_K;      // K, later h1
    float* s_V    = sm + SM_V;

    const int t    = threadIdx.x;
    const int w    = t >> 5, lane = t & 31;
    const int ag   = w >> 2, wn = w & 3;     // agent, N-warp
    const int e0g  = blockIdx.x * TB;

    // ---------------- P0: stage inputs (tf32-rounded) ----------------
    for (int i = t; i < TB * 90; i += THREADS) {
        int e = i / 90, rr = i - e * 90;
        int nn = rr / 30, dd = rr - nn * 30;
        s_in[(nn * TB + e) * LDIN + dd] =
            __uint_as_float(tf32r(obs[(long)(e0g + e) * 90 + rr]));
    }
    for (int i = t; i < TB * 27; i += THREADS) {
        int e = i / 27, rr = i - e * 27;
        int nn = rr / 9, dd = 30 + (rr - nn * 9);
        s_in[(nn * TB + e) * LDIN + dd] =
            __uint_as_float(tf32r(act[(long)(e0g + e) * 27 + rr]));
    }
    for (int i = t; i < 3 * TB * 9; i += THREADS) {  // zero k-slots 39..47
        int row = i / 9, kk = 39 + (i - (i/9)*9);
        s_in[row * LDIN + kk] = 0.f;
    }
    __syncthreads();

    // ---------------- P1: per-agent embeds (dual tensor, shared A) ----------------
    {
        float d1[2][4][4], d2[2][4][4];
        zero_d(d1); zero_d(d2);
        warp_gemm_dual<3,3>(s_in + ag*TB*LDIN, LDIN,
                            g_fragv + F_WO  + ag*1536 + wn*384,
                            g_fragv + F_WOA + ag*1536 + wn*384, lane, d1, d2);
        store_d(d1, s_oemb + ag*TB*LDA, LDA, b_o + ag*128, wn*32, lane, K_LKYRND);
        store_d(d2, s_oa   + ag*TB*LDA, LDA, b_oa + ag*128, wn*32, lane, K_LKYRND);
    }
    __syncthreads();

    // ---------------- P2a: K and V (dual tensor, shared A = oa_emb) ----------------
    {
        float d1[2][4][4], d2[2][4][4];
        zero_d(d1); zero_d(d2);
        warp_gemm_dual<8,8>(s_oa + ag*TB*LDA, LDA,
                            g_fragv + F_WK + wn*1024,
                            g_fragv + F_WV + wn*1024, lane, d1, d2);
        store_d(d1, s_K + ag*TB*LDA, LDA, bk, wn*32, lane, K_PLAIN);
        store_d(d2, s_V + ag*TB*LDA, LDA, bv, wn*32, lane, K_PLAIN);
    }
    __syncthreads();

    // ---------------- P2b: Q (oa region becomes Q) ----------------
    {
        float d[2][4][4];
        zero_d(d);
        warp_gemm<8,8>(s_oemb + ag*TB*LDA, LDA, g_fragv + F_WQ + wn*1024, lane, d);
        store_d(d, s_oa + ag*TB*LDA, LDA, bq, wn*32, lane, K_PLAIN);
    }
    __syncthreads();

    // ---------------- P3: 3-agent masked attention (scalar fp32) ----------------
    {
        const int n  = t >> 7;
        const int r  = t & 127;
        const int hg = r & 31, eg = r >> 5;
        const int h0 = hg * 4, eb = eg * 8;
        const float scale = 0.17677669529663689f;  // 1/sqrt(32)
        #pragma unroll
        for (int ei = 0; ei < 8; ei++) {
            const int e = eb + ei;
            float4 q  = *(float4*)&s_oa[(n*TB + e)*LDA + h0];
            float4 k0 = *(float4*)&s_K[(0*TB + e)*LDA + h0];
            float4 k1 = *(float4*)&s_K[(1*TB + e)*LDA + h0];
            float4 k2 = *(float4*)&s_K[(2*TB + e)*LDA + h0];
            float s0 = q.x*k0.x + q.y*k0.y + q.z*k0.z + q.w*k0.w;
            float s1 = q.x*k1.x + q.y*k1.y + q.z*k1.z + q.w*k1.w;
            float s2 = q.x*k2.x + q.y*k2.y + q.z*k2.z + q.w*k2.w;
            #pragma unroll
            for (int off = 4; off > 0; off >>= 1) {
                s0 += __shfl_xor_sync(0xffffffffu, s0, off);
                s1 += __shfl_xor_sync(0xffffffffu, s1, off);
                s2 += __shfl_xor_sync(0xffffffffu, s2, off);
            }
            s0 *= scale; s1 *= scale; s2 *= scale;
            if (n == 0)      s0 -= 1e10f;
            else if (n == 1) s1 -= 1e10f;
            else             s2 -= 1e10f;
            float mx  = fmaxf(s0, fmaxf(s1, s2));
            float p0  = __expf(s0 - mx);
            float p1  = __expf(s1 - mx);
            float p2  = __expf(s2 - mx);
            float inv = 1.0f / (p0 + p1 + p2);
            p0 *= inv; p1 *= inv; p2 *= inv;
            float4 v0 = *(float4*)&s_V[(0*TB + e)*LDA + h0];
            float4 v1 = *(float4*)&s_V[(1*TB + e)*LDA + h0];
            float4 v2 = *(float4*)&s_V[(2*TB + e)*LDA + h0];
            float4 ao;
            ao.x = __uint_as_float(tf32r(p0*v0.x + p1*v1.x + p2*v2.x));
            ao.y = __uint_as_float(tf32r(p0*v0.y + p1*v1.y + p2*v2.y));
            ao.z = __uint_as_float(tf32r(p0*v0.z + p1*v1.z + p2*v2.z));
            ao.w = __uint_as_float(tf32r(p0*v0.w + p1*v1.w + p2*v2.w));
            *(float4*)&s_oa[(n*TB + e)*LDA + h0] = ao;   // attn_out
        }
    }
    __syncthreads();

    // ---------------- P4: critic layer 1 (tensor, 256 -> 128) ----------------
    {
        float d[2][4][4];
        zero_d(d);
        const uint4* fc = g_fragv + F_WC1 + ag*8192 + wn*2048;   // KPT=16
        warp_gemm<8,16>(s_oemb + ag*TB*LDA, LDA, fc, lane, d);
        warp_gemm<8,16>(s_oa   + ag*TB*LDA, LDA, fc + 8*32, lane, d);
        store_d(d, s_K + ag*TB*LDA, LDA, bc1 + ag*128, wn*32, lane, K_LKYRND);  // h1
    }
    __syncthreads();

    // ---------------- P5a: critic layer 2 (tensor, 128 -> 16pad) partials ----------------
    {
        const int nt = wn & 1, kph = wn >> 1;
        const int ra = lane >> 2, ca = lane & 3;
        float d[2][4];
        #pragma unroll
        for (int mt = 0; mt < 2; mt++)
            #pragma unroll
            for (int i = 0; i < 4; i++) d[mt][i] = 0.f;
        const float* Ab = s_K + ag*TB*LDA;
        const uint4* fc = g_fragv + F_WC2 + ag*512 + nt*256;
        #pragma unroll
        for (int kp2 = 0; kp2 < 4; kp2++) {
            const int kp = kph*4 + kp2;
            unsigned a[2][2][4];
            LOAD_AFRAG(a, Ab, LDA, kp);
            uint4 b = fc[kp*32 + lane];
            #pragma unroll
            for (int mt = 0; mt < 2; mt++) {
                mma8(d[mt], a[mt][0], b.x, b.y);
                mma8(d[mt], a[mt][1], b.z, b.w);
            }
        }
        // partials into s_in scratch: [ag][kph][row(32)][20]
        float* pp = s_in + (ag*2 + kph) * TB * 20;
        const int rr = lane >> 2, cc = (lane & 3)*2, col = nt*8 + cc;
        #pragma unroll
        for (int mt = 0; mt < 2; mt++) {
            *(float2*)&pp[(rr + mt*16)*20 + col]     = make_float2(d[mt][0], d[mt][1]);
            *(float2*)&pp[(rr + 8 + mt*16)*20 + col] = make_float2(d[mt][2], d[mt][3]);
        }
        (void)ca; (void)ra;
    }
    __syncthreads();

    // ---------------- P5b: reduce partials + bias + store ----------------
    for (int idx = t; idx < TB * 27; idx += THREADS) {
        int e = idx / 27, rr = idx - e * 27;
        int nn = rr / 9,  a = rr - nn * 9;
        float v = s_in[(nn*2 + 0)*TB*20 + e*20 + a]
                + s_in[(nn*2 + 1)*TB*20 + e*20 + a]
                + bc2[nn*9 + a];
        out[(long)(e0g + e) * 27 + rr] = v;
    }
}

extern "C" void kernel_launch(void* const* d_in, const int* in_sizes, int n_in,
                              void* d_out, int out_size) {
    const float* obs  = (const float*)d_in[0];
    const float* act  = (const float*)d_in[1];
    const float* W_o  = (const float*)d_in[2];
    const float* b_o  = (const float*)d_in[3];
    const float* W_oa = (const float*)d_in[4];
    const float* b_oa = (const float*)d_in[5];
    const float* Wq   = (const float*)d_in[6];
    const float* bq   = (const float*)d_in[7];
    const float* Wk   = (const float*)d_in[8];
    const float* bk   = (const float*)d_in[9];
    const float* Wv   = (const float*)d_in[10];
    const float* bv   = (const float*)d_in[11];
    const float* Wc1  = (const float*)d_in[12];
    const float* bc1  = (const float*)d_in[13];
    const float* Wc2  = (const float*)d_in[14];
    const float* bc2  = (const float*)d_in[15];
    float* out = (float*)d_out;

    const int batch = in_sizes[0] / (3 * 30);   // 131072
    const int grid  = batch / TB;               // 4096
    const size_t smem = SMEM_FLOATS * sizeof(float);  // 217.5 KB

    prep_kernel<<<744, 256>>>(W_o, W_oa, Wq, Wk, Wv, Wc1, Wc2);

    cudaFuncSetAttribute(valuenet_kernel,
                         cudaFuncAttributeMaxDynamicSharedMemorySize, (int)smem);
    valuenet_kernel<<<grid, THREADS, smem>>>(
        obs, act, b_o, b_oa, bq, bk, bv, bc1, bc2, out);
}